// round 11
// baseline (speedup 1.0000x reference)
#include <cuda_runtime.h>
#include <cuda_bf16.h>
#include <math.h>

// Problem constants
#define BB 16
#define NPTS 1000
#define KDIM 16384         // C*64 (fc1 input)
#define H1DIM 1024
#define MDIM 2000          // P*K*2
#define FDIM 258

// Output layout: refined [32000] @0, v [320] @32000, init [32000] @32320
#define OUT_V    32000
#define OUT_INIT 32320

// ---------------- packed f32x2 helpers (SASS FFMA2 path) ----------------
typedef unsigned long long u64p;
__device__ __forceinline__ u64p pack2(float lo, float hi) {
    u64p r; asm("mov.b64 %0, {%1,%2};" : "=l"(r) : "f"(lo), "f"(hi)); return r;
}
__device__ __forceinline__ float2 unpack2(u64p v) {
    float2 r; asm("mov.b64 {%0,%1}, %2;" : "=f"(r.x), "=f"(r.y) : "l"(v)); return r;
}
#define FMA2(d, a, b, c) asm("fma.rn.f32x2 %0, %1, %2, %3;" : "=l"(d) : "l"(a), "l"(b), "l"(c))

__device__ __forceinline__ unsigned int smem_u32(const void* p) {
    unsigned int a;
    asm("{ .reg .u64 t; cvta.to.shared.u64 t, %1; cvt.u32.u64 %0, t; }" : "=r"(a) : "l"(p));
    return a;
}

// ---------------- scratch ----------------
__device__ float g_flat[BB * KDIM];                    // pooled [b][k]
__device__ float g_hpart[128 * BB * H1DIM];            // fc1 partials [ks][b][n]
__device__ float g_h[BB * H1DIM];                      // relu(h) [b][n]
__device__ float g_logpart[32 * BB * 2048];            // fc2 partials [ks][b][m pad]
__device__ float g_feat[(size_t)BB * FDIM * 1024];     // [b][k(258)][pt pad 1024]
__device__ float g_R1t[FDIM * 128];                    // R1^T [k][n]
__device__ float g_R2t[128 * 64];                      // R2^T [k][n]
__device__ int   g_done[BB];                           // per-batch gather completion flags

// ---------------- 1) avg pool (+ prep transposes merged) ----------------
__global__ void pool_kernel(const float* __restrict__ p4,
                            const float* __restrict__ R1, const float* __restrict__ R2) {
    cudaTriggerProgrammaticLaunchCompletion();
    if (blockIdx.x < 1024) {
        int idx = blockIdx.x * 256 + threadIdx.x;
        int j = idx & 7, i = (idx >> 3) & 7;
        int bc = idx >> 6;
        const float* base = p4 + (size_t)bc * 1024 + i * 128 + j * 4;
        float s = 0.f;
#pragma unroll
        for (int di = 0; di < 4; di++) {
            float4 v = *(const float4*)(base + di * 32);
            s += v.x + v.y + v.z + v.w;
        }
        g_flat[idx] = s * (1.0f / 16.0f);
    } else {
        int idx = (blockIdx.x - 1024) * 256 + threadIdx.x;
        if (idx < FDIM * 128) {
            int k = idx >> 7, n = idx & 127;
            g_R1t[idx] = R1[n * FDIM + k];
        } else if (idx < FDIM * 128 + 128 * 64) {
            int i = idx - FDIM * 128;
            int k = i >> 6, n = i & 63;
            g_R2t[i] = R2[n * 128 + k];
        }
    }
}

// ---------------- 2) FC1: 512 n x 128 k-slice per block, grid (128,2) ----------------
#define FC1_SW_STRIDE 33
#define FC1_SF_STRIDE 18
__global__ void fc1_kernel(const float* __restrict__ W1) {
    extern __shared__ float sm1[];
    float* sW = sm1;                         // [512 n][33]
    float* sf = sm1 + 512 * FC1_SW_STRIDE;   // [128 k][18]
    int tid = threadIdx.x;
    int ks = blockIdx.x;
    int k0 = ks * 128;
    int nb = blockIdx.y * 512;

    // pre-sync prologue: W1 chunk 0 (input only; overlaps pool)
#pragma unroll
    for (int t = 0; t < 16; t++) {
        int f = tid + t * 256;
        int r = f >> 3, c = f & 7;
        float4 v = *(const float4*)&W1[(size_t)(nb + r) * KDIM + k0 + c * 4];
        float* d = &sW[r * FC1_SW_STRIDE + c * 4];
        d[0] = v.x; d[1] = v.y; d[2] = v.z; d[3] = v.w;
    }
    cudaGridDependencySynchronize();
    cudaTriggerProgrammaticLaunchCompletion();

#pragma unroll
    for (int t = 0; t < 8; t++) {
        int e = tid + t * 256;
        int b = e >> 7, kk = e & 127;
        sf[kk * FC1_SF_STRIDE + b] = g_flat[b * KDIM + k0 + kk];
    }
    __syncthreads();

    u64p acc[2][8];
#pragma unroll
    for (int r = 0; r < 2; r++)
#pragma unroll
        for (int j = 0; j < 8; j++) acc[r][j] = 0;

    for (int kc = 0; kc < 128; kc += 32) {
#pragma unroll 4
        for (int kk = 0; kk < 32; kk++) {
            float w0 = sW[tid * FC1_SW_STRIDE + kk];
            float w1 = sW[(tid + 256) * FC1_SW_STRIDE + kk];
            u64p w20 = pack2(w0, w0), w21 = pack2(w1, w1);
            const u64p* fl = (const u64p*)&sf[(kc + kk) * FC1_SF_STRIDE];
#pragma unroll
            for (int j = 0; j < 8; j++) {
                u64p f = fl[j];
                FMA2(acc[0][j], f, w20, acc[0][j]);
                FMA2(acc[1][j], f, w21, acc[1][j]);
            }
        }
        if (kc < 96) {
            __syncthreads();
#pragma unroll
            for (int t = 0; t < 16; t++) {
                int f = tid + t * 256;
                int r = f >> 3, c = f & 7;
                float4 v = *(const float4*)&W1[(size_t)(nb + r) * KDIM + k0 + kc + 32 + c * 4];
                float* d = &sW[r * FC1_SW_STRIDE + c * 4];
                d[0] = v.x; d[1] = v.y; d[2] = v.z; d[3] = v.w;
            }
            __syncthreads();
        }
    }
#pragma unroll
    for (int r = 0; r < 2; r++) {
        int n = nb + tid + r * 256;
#pragma unroll
        for (int j = 0; j < 8; j++) {
            float2 v = unpack2(acc[r][j]);
            g_hpart[(ks * 16 + 2 * j + 0) * H1DIM + n] = v.x;
            g_hpart[(ks * 16 + 2 * j + 1) * H1DIM + n] = v.y;
        }
    }
}

// ---------------- 2b) reduce 128 partials: float4-coalesced + shfl over 8 lanes ----------------
__global__ void reduce_h_kernel(const float* __restrict__ b1) {
    cudaGridDependencySynchronize();
    cudaTriggerProgrammaticLaunchCompletion();
    int gid = blockIdx.x * 256 + threadIdx.x;   // 0..32767
    int lane = gid & 31;
    int warp = gid >> 5;                         // 0..1023
    int f4 = warp * 4 + (lane & 3);              // 0..4095 (float4 index into g_h)
    int sp0 = lane >> 2;                          // 0..7
    const float4* hp = (const float4*)g_hpart;   // [128][4096]
    float4 s = make_float4(0.f, 0.f, 0.f, 0.f);
#pragma unroll
    for (int t = 0; t < 16; t++) {
        float4 v = hp[(sp0 + t * 8) * 4096 + f4];
        s.x += v.x; s.y += v.y; s.z += v.z; s.w += v.w;
    }
#pragma unroll
    for (int d = 4; d <= 16; d <<= 1) {
        s.x += __shfl_xor_sync(0xFFFFFFFFu, s.x, d);
        s.y += __shfl_xor_sync(0xFFFFFFFFu, s.y, d);
        s.z += __shfl_xor_sync(0xFFFFFFFFu, s.z, d);
        s.w += __shfl_xor_sync(0xFFFFFFFFu, s.w, d);
    }
    if ((lane >> 2) == 0) {
        int n0 = (f4 * 4) & 1023;
        float4 r;
        r.x = fmaxf(s.x + b1[n0 + 0], 0.f);
        r.y = fmaxf(s.y + b1[n0 + 1], 0.f);
        r.z = fmaxf(s.z + b1[n0 + 2], 0.f);
        r.w = fmaxf(s.w + b1[n0 + 3], 0.f);
        ((float4*)g_h)[f4] = r;
    }
}

// ---------------- 3) FC2: 256 m-tile x 32 k-slice, grid (8,32) ----------------
#define FC2_SWT_STRIDE 257
#define FC2_SH_STRIDE 18
__global__ void fc2_kernel(const float* __restrict__ W2) {
    extern __shared__ float sm2[];
    float* sWt = sm2;                        // [32 k][257]
    float* sh  = sm2 + 32 * FC2_SWT_STRIDE;  // [32 k][18]
    int tid = threadIdx.x;
    int m0 = blockIdx.x * 256;
    int ks = blockIdx.y;
    int k0 = ks * 32;
    int m = m0 + tid;

    // pre-sync prologue: W2 tile -> smem transposed (input only)
#pragma unroll
    for (int i = 0; i < 8; i++) {
        int f = tid + i * 256;
        int row = f >> 3, c = (f & 7) * 4;
        int mr = m0 + row;
        float4 v = make_float4(0.f, 0.f, 0.f, 0.f);
        if (mr < MDIM) v = *(const float4*)&W2[(size_t)mr * H1DIM + k0 + c];
        sWt[(c + 0) * FC2_SWT_STRIDE + row] = v.x;
        sWt[(c + 1) * FC2_SWT_STRIDE + row] = v.y;
        sWt[(c + 2) * FC2_SWT_STRIDE + row] = v.z;
        sWt[(c + 3) * FC2_SWT_STRIDE + row] = v.w;
    }
    cudaGridDependencySynchronize();
    cudaTriggerProgrammaticLaunchCompletion();

#pragma unroll
    for (int t = 0; t < 2; t++) {
        int e = tid + t * 256;
        int kk = e & 31, b = e >> 5;
        sh[kk * FC2_SH_STRIDE + b] = g_h[b * H1DIM + k0 + kk];
    }
    __syncthreads();

    u64p acc[8];
#pragma unroll
    for (int j = 0; j < 8; j++) acc[j] = 0;

#pragma unroll 4
    for (int kk = 0; kk < 32; kk++) {
        float w = sWt[kk * FC2_SWT_STRIDE + tid];
        u64p w2 = pack2(w, w);
        const u64p* fl = (const u64p*)&sh[kk * FC2_SH_STRIDE];
#pragma unroll
        for (int j = 0; j < 8; j++) FMA2(acc[j], fl[j], w2, acc[j]);
    }
    if (m < MDIM) {
#pragma unroll
        for (int j = 0; j < 8; j++) {
            float2 v = unpack2(acc[j]);
            g_logpart[(ks * 16 + 2 * j + 0) * 2048 + m] = v.x;
            g_logpart[(ks * 16 + 2 * j + 1) * 2048 + m] = v.y;
        }
    }
}

// ---------------- 4) epilogue: trigger at entry (gather prefetch overlaps) ----------------
__global__ void epi_kernel(const float* __restrict__ b2, float* __restrict__ out) {
    cudaTriggerProgrammaticLaunchCompletion();   // successor (gather) prologue reads p2 only
    cudaGridDependencySynchronize();
    // reset per-batch gather flags (before any gather block's post-sync work runs)
    if (blockIdx.x == 0 && threadIdx.x < BB) g_done[threadIdx.x] = 0;
    int gid = blockIdx.x * 256 + threadIdx.x;   // 0..255999
    int e = gid >> 3;
    int r = gid & 7;
    int b = e / MDIM, m = e - b * MDIM;
    float s = 0.f;
#pragma unroll
    for (int t = 0; t < 4; t++) s += g_logpart[((r + t * 8) * 16 + b) * 2048 + m];
    s += __shfl_xor_sync(0xFFFFFFFFu, s, 1);
    s += __shfl_xor_sync(0xFFFFFFFFu, s, 2);
    s += __shfl_xor_sync(0xFFFFFFFFu, s, 4);
    if (r == 0) {
        float v = 1.f / (1.f + expf(-(s + b2[m])));
        out[OUT_INIT + b * MDIM + m] = v;
        int pt = m >> 1, c = m & 1;
        g_feat[((size_t)b * FDIM + 256 + c) * 1024 + pt] = v;
    }
}

// ---------------- 5) bilinear gather: cp.async image prefetch + per-b flag ----------------
__global__ void gather_kernel(const float* __restrict__ p2, const float* __restrict__ out) {
    extern __shared__ float img[];               // 64KB
    int bc = blockIdx.x;
    int b = bc >> 8;
    int tid = threadIdx.x;

    // pre-sync prologue: image -> smem via cp.async (input only)
    unsigned int sbase = smem_u32(img);
    const char* gsrc = (const char*)(p2 + (size_t)bc * 16384);
#pragma unroll
    for (int t = 0; t < 16; t++) {
        int off = (tid + t * 256) * 16;
        asm volatile("cp.async.cg.shared.global [%0], [%1], 16;"
                     :: "r"(sbase + off), "l"(gsrc + off) : "memory");
    }
    asm volatile("cp.async.commit_group;" ::: "memory");
    cudaGridDependencySynchronize();
    cudaTriggerProgrammaticLaunchCompletion();

    const float* initp = out + OUT_INIT + b * MDIM;
    float px[4], py[4];
#pragma unroll
    for (int t = 0; t < 4; t++) {
        int pt = tid + t * 256;
        if (pt < NPTS) { px[t] = initp[pt * 2 + 0]; py[t] = initp[pt * 2 + 1]; }
    }
    asm volatile("cp.async.wait_group 0;" ::: "memory");
    __syncthreads();

    float* frow = &g_feat[((size_t)b * FDIM + (bc & 255)) * 1024];
#pragma unroll
    for (int t = 0; t < 4; t++) {
        int pt = tid + t * 256;
        if (pt < NPTS) {
            float x = px[t] * 128.f - 0.5f;
            float y = py[t] * 128.f - 0.5f;
            float x0f = floorf(x), y0f = floorf(y);
            int x0 = (int)x0f, y0 = (int)y0f;
            float wx = x - x0f, wy = y - y0f;
            bool xv0 = (x0 >= 0) & (x0 <= 127);
            bool xv1 = (x0 + 1 >= 0) & (x0 + 1 <= 127);
            bool yv0 = (y0 >= 0) & (y0 <= 127);
            bool yv1 = (y0 + 1 >= 0) & (y0 + 1 <= 127);
            int x0c = min(max(x0, 0), 127), x1c = min(max(x0 + 1, 0), 127);
            int y0c = min(max(y0, 0), 127), y1c = min(max(y0 + 1, 0), 127);
            float v00 = (xv0 && yv0) ? img[y0c * 128 + x0c] : 0.f;
            float v10 = (xv1 && yv0) ? img[y0c * 128 + x1c] : 0.f;
            float v01 = (xv0 && yv1) ? img[y1c * 128 + x0c] : 0.f;
            float v11 = (xv1 && yv1) ? img[y1c * 128 + x1c] : 0.f;
            frow[pt] = v00 * (1.f - wx) * (1.f - wy) + v10 * wx * (1.f - wy)
                     + v01 * (1.f - wx) * wy        + v11 * wx * wy;
        }
    }
    // signal this (b,c) channel done
    __syncthreads();
    __threadfence();
    if (tid == 0) atomicAdd(&g_done[b], 1);
}

// ---------------- 6) refine MLP: flag-gated (no gridsync), streamed k-chunks ----------------
// Dispatch begins once all gather blocks passed their trigger (=> epi complete);
// per-b flags gate g_feat channel rows. Deadlock-free: all gather blocks are
// already resident/finished when the first refine block lands.
__global__ void refine_kernel(const float* __restrict__ rb1,
                              const float* __restrict__ rb2,
                              const float* __restrict__ R3, const float* __restrict__ rb3,
                              float* __restrict__ out) {
    extern __shared__ float smr[];
    float* sh1    = smr;            // [128][64]
    float* sfeatc = smr + 8192;     // [32][64]   (layer1)  | sR2t overlays @8192 (layer2)
    float* sR1    = smr + 10240;    // [32][128]  (layer1)
    float* scoord = smr + 14336;    // [2][64]
    float* sR2t   = smr + 8192;     // [128][64]  (layer2)
    float* sh2    = smr + 16384;    // [64][64]
    float* sR3    = smr + 20480;    // [128]

    int tid = threadIdx.x;
    int b = blockIdx.y;
    int p0 = blockIdx.x * 64;
    int pg = tid & 15;
    int ng = tid >> 4;
    int n0 = ng * 8;

    cudaTriggerProgrammaticLaunchCompletion();   // value's prologue reads V1 only

    // prologue: coord rows (epi complete at our dispatch), R3, R1 chunk 0 (pool)
    if (tid < 128) {
        scoord[tid] = g_feat[((size_t)b * FDIM + 256 + (tid >> 6)) * 1024 + p0 + (tid & 63)];
        sR3[tid] = R3[tid];
    }
#pragma unroll
    for (int t = 0; t < 4; t++) {
        int f = tid + t * 256;
        ((float4*)sR1)[f] = ((const float4*)g_R1t)[f];
    }

    // wait for this batch's 256 gather channels
    if (tid == 0) {
        while (((volatile int*)g_done)[b] < 256) __nanosleep(100);
    }
    __syncthreads();
    __threadfence();

    u64p acc[8][2];
#pragma unroll
    for (int r = 0; r < 8; r++) { acc[r][0] = 0; acc[r][1] = 0; }

    for (int kc = 0; kc < 256; kc += 32) {
        __syncthreads();
#pragma unroll
        for (int t = 0; t < 2; t++) {
            int f = tid + t * 256;
            int row = f >> 4, col = f & 15;
            ((float4*)sfeatc)[row * 16 + col] =
                *(const float4*)&g_feat[((size_t)b * FDIM + kc + row) * 1024 + p0 + col * 4];
        }
        if (kc > 0) {
#pragma unroll
            for (int t = 0; t < 4; t++) {
                int f = tid + t * 256;
                ((float4*)sR1)[f] = ((const float4*)(g_R1t + kc * 128))[f];
            }
        }
        __syncthreads();
#pragma unroll 2
        for (int kk = 0; kk < 32; kk++) {
            u64p w2[8];
#pragma unroll
            for (int r = 0; r < 8; r += 4) {
                float4 w4 = *(const float4*)&sR1[kk * 128 + n0 + r];
                w2[r + 0] = pack2(w4.x, w4.x); w2[r + 1] = pack2(w4.y, w4.y);
                w2[r + 2] = pack2(w4.z, w4.z); w2[r + 3] = pack2(w4.w, w4.w);
            }
            ulonglong2 f = *(const ulonglong2*)&sfeatc[kk * 64 + pg * 4];
#pragma unroll
            for (int r = 0; r < 8; r++) {
                FMA2(acc[r][0], f.x, w2[r], acc[r][0]);
                FMA2(acc[r][1], f.y, w2[r], acc[r][1]);
            }
        }
    }
#pragma unroll
    for (int kr = 0; kr < 2; kr++) {
        ulonglong2 f = *(const ulonglong2*)&scoord[kr * 64 + pg * 4];
#pragma unroll
        for (int r = 0; r < 8; r++) {
            float w = g_R1t[(256 + kr) * 128 + n0 + r];
            u64p w2 = pack2(w, w);
            FMA2(acc[r][0], f.x, w2, acc[r][0]);
            FMA2(acc[r][1], f.y, w2, acc[r][1]);
        }
    }
#pragma unroll
    for (int r = 0; r < 8; r++) {
        float bias = rb1[n0 + r];
        float2 v0 = unpack2(acc[r][0]), v1 = unpack2(acc[r][1]);
        float* d = &sh1[(n0 + r) * 64 + pg * 4];
        d[0] = fmaxf(v0.x + bias, 0.f); d[1] = fmaxf(v0.y + bias, 0.f);
        d[2] = fmaxf(v1.x + bias, 0.f); d[3] = fmaxf(v1.y + bias, 0.f);
    }
    __syncthreads();

    // ---- layer 2 ----
#pragma unroll
    for (int t = 0; t < 8; t++) {
        int f = tid + t * 256;
        ((float4*)sR2t)[f] = ((const float4*)g_R2t)[f];
    }
    __syncthreads();

    int n2 = ng * 4;
    u64p acc2[4][2];
#pragma unroll
    for (int r = 0; r < 4; r++) { acc2[r][0] = 0; acc2[r][1] = 0; }
#pragma unroll 2
    for (int kk = 0; kk < 128; kk++) {
        float4 w4 = *(const float4*)&sR2t[kk * 64 + n2];
        u64p w2[4] = { pack2(w4.x, w4.x), pack2(w4.y, w4.y),
                       pack2(w4.z, w4.z), pack2(w4.w, w4.w) };
        ulonglong2 f = *(const ulonglong2*)&sh1[kk * 64 + pg * 4];
#pragma unroll
        for (int r = 0; r < 4; r++) {
            FMA2(acc2[r][0], f.x, w2[r], acc2[r][0]);
            FMA2(acc2[r][1], f.y, w2[r], acc2[r][1]);
        }
    }
#pragma unroll
    for (int r = 0; r < 4; r++) {
        float bias = rb2[n2 + r];
        float2 v0 = unpack2(acc2[r][0]), v1 = unpack2(acc2[r][1]);
        float* d = &sh2[(n2 + r) * 64 + pg * 4];
        d[0] = fmaxf(v0.x + bias, 0.f); d[1] = fmaxf(v0.y + bias, 0.f);
        d[2] = fmaxf(v1.x + bias, 0.f); d[3] = fmaxf(v1.y + bias, 0.f);
    }
    __syncthreads();

    if (tid < 128) {
        int c = tid >> 6, pp = tid & 63;
        float a = rb3[c];
#pragma unroll 8
        for (int k = 0; k < 64; k++) a += sh2[k * 64 + pp] * sR3[c * 64 + k];
        float disp = tanhf(a);
        int ptg = p0 + pp;
        if (ptg < NPTS) {
            float iv = out[OUT_INIT + b * MDIM + ptg * 2 + c];
            float r = fminf(fmaxf(iv + 0.1f * disp, 0.f), 1.f);
            out[(b * NPTS + ptg) * 2 + c] = r;
        }
    }
}

// ---------------- 7) value head ----------------
__global__ void value_kernel(const float* __restrict__ V1, const float* __restrict__ vb1,
                             const float* __restrict__ V2, const float* __restrict__ vb2,
                             float* __restrict__ out) {
    extern __shared__ float sv[];
    float* spf  = sv;
    float* sV1  = sv + 128;
    float* sred = sv + 128 + 12800;
    int bp = blockIdx.x;
    int tid = threadIdx.x;

    const float4* v4 = (const float4*)V1;
    float4* s4 = (float4*)sV1;
#pragma unroll
    for (int t = 0; t < 25; t++) s4[tid + t * 128] = v4[tid + t * 128];
    cudaGridDependencySynchronize();

    if (tid < 100) spf[tid] = out[bp * 100 + tid];
    __syncthreads();
    float a = vb1[tid];
#pragma unroll 4
    for (int k = 0; k < 100; k++) a += spf[k] * sV1[tid * 100 + k];
    sred[tid] = fmaxf(a, 0.f) * V2[tid];
    __syncthreads();
#pragma unroll
    for (int s = 64; s > 0; s >>= 1) {
        if (tid < s) sred[tid] += sred[tid + s];
        __syncthreads();
    }
    if (tid == 0) out[OUT_V + bp] = 1.f / (1.f + expf(-(sred[0] + vb2[0])));
}

// ---------------- launch ----------------
extern "C" void kernel_launch(void* const* d_in, const int* in_sizes, int n_in,
                              void* d_out, int out_size) {
    const float* p4   = (const float*)d_in[0];
    const float* p2   = (const float*)d_in[1];
    const float* W1   = (const float*)d_in[3];
    const float* b1   = (const float*)d_in[4];
    const float* W2   = (const float*)d_in[5];
    const float* b2   = (const float*)d_in[6];
    const float* R1   = (const float*)d_in[7];
    const float* rb1  = (const float*)d_in[8];
    const float* R2   = (const float*)d_in[9];
    const float* rb2  = (const float*)d_in[10];
    const float* R3   = (const float*)d_in[11];
    const float* rb3  = (const float*)d_in[12];
    const float* V1   = (const float*)d_in[13];
    const float* vb1  = (const float*)d_in[14];
    const float* V2   = (const float*)d_in[15];
    const float* vb2  = (const float*)d_in[16];
    float* out = (float*)d_out;

    const int FC1_SMEM = (512 * FC1_SW_STRIDE + 128 * FC1_SF_STRIDE) * 4;   // 76800
    const int FC2_SMEM = (32 * FC2_SWT_STRIDE + 32 * FC2_SH_STRIDE) * 4;    // 35200
    const int RFN_SMEM = 20608 * 4;                                         // 82432

    cudaFuncSetAttribute(fc1_kernel,    cudaFuncAttributeMaxDynamicSharedMemorySize, FC1_SMEM);
    cudaFuncSetAttribute(fc2_kernel,    cudaFuncAttributeMaxDynamicSharedMemorySize, FC2_SMEM);
    cudaFuncSetAttribute(gather_kernel, cudaFuncAttributeMaxDynamicSharedMemorySize, 65536);
    cudaFuncSetAttribute(refine_kernel, cudaFuncAttributeMaxDynamicSharedMemorySize, RFN_SMEM);
    cudaFuncSetAttribute(value_kernel,  cudaFuncAttributeMaxDynamicSharedMemorySize, 52224);

    cudaLaunchAttribute pdl[1];
    pdl[0].id = cudaLaunchAttributeProgrammaticStreamSerialization;
    pdl[0].val.programmaticStreamSerializationAllowed = 1;

    pool_kernel<<<1186, 256>>>(p4, R1, R2);

    cudaLaunchConfig_t cfg = {};
    cfg.blockDim = {256, 1, 1};
    cfg.stream = 0;
    cfg.attrs = pdl;
    cfg.numAttrs = 1;

    cfg.gridDim = {128, 2, 1};  cfg.dynamicSmemBytes = FC1_SMEM;
    cudaLaunchKernelEx(&cfg, fc1_kernel, W1);
    cfg.gridDim = {128, 1, 1};  cfg.dynamicSmemBytes = 0;
    cudaLaunchKernelEx(&cfg, reduce_h_kernel, b1);
    cfg.gridDim = {8, 32, 1};   cfg.dynamicSmemBytes = FC2_SMEM;
    cudaLaunchKernelEx(&cfg, fc2_kernel, W2);
    cfg.gridDim = {1000, 1, 1}; cfg.dynamicSmemBytes = 0;
    cudaLaunchKernelEx(&cfg, epi_kernel, b2, out);
    cfg.gridDim = {4096, 1, 1}; cfg.dynamicSmemBytes = 65536;
    cudaLaunchKernelEx(&cfg, gather_kernel, p2, out);
    cfg.gridDim = {16, 16, 1};  cfg.dynamicSmemBytes = RFN_SMEM;
    cudaLaunchKernelEx(&cfg, refine_kernel, rb1, rb2, R3, rb3, out);
    cfg.gridDim = {320, 1, 1};  cfg.blockDim = {128, 1, 1}; cfg.dynamicSmemBytes = 52224;
    cudaLaunchKernelEx(&cfg, value_kernel, V1, vb1, V2, vb2, out);
}

// round 13
// speedup vs baseline: 1.0360x; 1.0360x over previous
#include <cuda_runtime.h>
#include <cuda_bf16.h>
#include <math.h>

// Problem constants
#define BB 16
#define NPTS 1000
#define KDIM 16384         // C*64 (fc1 input)
#define H1DIM 1024
#define MDIM 2000          // P*K*2
#define FDIM 258

// Output layout: refined [32000] @0, v [320] @32000, init [32000] @32320
#define OUT_V    32000
#define OUT_INIT 32320

// ---------------- packed f32x2 helpers (SASS FFMA2 path) ----------------
typedef unsigned long long u64p;
__device__ __forceinline__ u64p pack2(float lo, float hi) {
    u64p r; asm("mov.b64 %0, {%1,%2};" : "=l"(r) : "f"(lo), "f"(hi)); return r;
}
__device__ __forceinline__ float2 unpack2(u64p v) {
    float2 r; asm("mov.b64 {%0,%1}, %2;" : "=f"(r.x), "=f"(r.y) : "l"(v)); return r;
}
#define FMA2(d, a, b, c) asm("fma.rn.f32x2 %0, %1, %2, %3;" : "=l"(d) : "l"(a), "l"(b), "l"(c))

__device__ __forceinline__ unsigned int smem_u32(const void* p) {
    unsigned int a;
    asm("{ .reg .u64 t; cvta.to.shared.u64 t, %1; cvt.u32.u64 %0, t; }" : "=r"(a) : "l"(p));
    return a;
}

// ---------------- scratch ----------------
__device__ float g_flat[BB * KDIM];                    // pooled [b][k]
__device__ float g_hpart[128 * BB * H1DIM];            // fc1 partials [ks][b][n]
__device__ float g_h[BB * H1DIM];                      // relu(h) [b][n]
__device__ float g_logpart[32 * BB * 2048];            // fc2 partials [ks][b][m pad]
__device__ float g_feat[(size_t)BB * FDIM * 1024];     // [b][k(258)][pt pad 1024]
__device__ float g_R1t[FDIM * 128];                    // R1^T [k][n]
__device__ float g_R2t[128 * 64];                      // R2^T [k][n]

// ---------------- 1) avg pool (+ prep transposes merged) ----------------
__global__ void pool_kernel(const float* __restrict__ p4,
                            const float* __restrict__ R1, const float* __restrict__ R2) {
    cudaTriggerProgrammaticLaunchCompletion();
    if (blockIdx.x < 1024) {
        int idx = blockIdx.x * 256 + threadIdx.x;
        int j = idx & 7, i = (idx >> 3) & 7;
        int bc = idx >> 6;
        const float* base = p4 + (size_t)bc * 1024 + i * 128 + j * 4;
        float s = 0.f;
#pragma unroll
        for (int di = 0; di < 4; di++) {
            float4 v = *(const float4*)(base + di * 32);
            s += v.x + v.y + v.z + v.w;
        }
        g_flat[idx] = s * (1.0f / 16.0f);
    } else {
        int idx = (blockIdx.x - 1024) * 256 + threadIdx.x;
        if (idx < FDIM * 128) {
            int k = idx >> 7, n = idx & 127;
            g_R1t[idx] = R1[n * FDIM + k];
        } else if (idx < FDIM * 128 + 128 * 64) {
            int i = idx - FDIM * 128;
            int k = i >> 6, n = i & 63;
            g_R2t[i] = R2[n * 128 + k];
        }
    }
}

// ---------------- 2) FC1: 512 n x 128 k-slice per block, grid (128,2) ----------------
#define FC1_SW_STRIDE 33
#define FC1_SF_STRIDE 18
__global__ void fc1_kernel(const float* __restrict__ W1) {
    extern __shared__ float sm1[];
    float* sW = sm1;                         // [512 n][33]
    float* sf = sm1 + 512 * FC1_SW_STRIDE;   // [128 k][18]
    int tid = threadIdx.x;
    int ks = blockIdx.x;
    int k0 = ks * 128;
    int nb = blockIdx.y * 512;

    // pre-sync prologue: W1 chunk 0 (input only; overlaps pool)
#pragma unroll
    for (int t = 0; t < 16; t++) {
        int f = tid + t * 256;
        int r = f >> 3, c = f & 7;
        float4 v = *(const float4*)&W1[(size_t)(nb + r) * KDIM + k0 + c * 4];
        float* d = &sW[r * FC1_SW_STRIDE + c * 4];
        d[0] = v.x; d[1] = v.y; d[2] = v.z; d[3] = v.w;
    }
    cudaGridDependencySynchronize();
    cudaTriggerProgrammaticLaunchCompletion();

#pragma unroll
    for (int t = 0; t < 8; t++) {
        int e = tid + t * 256;
        int b = e >> 7, kk = e & 127;
        sf[kk * FC1_SF_STRIDE + b] = g_flat[b * KDIM + k0 + kk];
    }
    __syncthreads();

    u64p acc[2][8];
#pragma unroll
    for (int r = 0; r < 2; r++)
#pragma unroll
        for (int j = 0; j < 8; j++) acc[r][j] = 0;

    for (int kc = 0; kc < 128; kc += 32) {
#pragma unroll 4
        for (int kk = 0; kk < 32; kk++) {
            float w0 = sW[tid * FC1_SW_STRIDE + kk];
            float w1 = sW[(tid + 256) * FC1_SW_STRIDE + kk];
            u64p w20 = pack2(w0, w0), w21 = pack2(w1, w1);
            const u64p* fl = (const u64p*)&sf[(kc + kk) * FC1_SF_STRIDE];
#pragma unroll
            for (int j = 0; j < 8; j++) {
                u64p f = fl[j];
                FMA2(acc[0][j], f, w20, acc[0][j]);
                FMA2(acc[1][j], f, w21, acc[1][j]);
            }
        }
        if (kc < 96) {
            __syncthreads();
#pragma unroll
            for (int t = 0; t < 16; t++) {
                int f = tid + t * 256;
                int r = f >> 3, c = f & 7;
                float4 v = *(const float4*)&W1[(size_t)(nb + r) * KDIM + k0 + kc + 32 + c * 4];
                float* d = &sW[r * FC1_SW_STRIDE + c * 4];
                d[0] = v.x; d[1] = v.y; d[2] = v.z; d[3] = v.w;
            }
            __syncthreads();
        }
    }
#pragma unroll
    for (int r = 0; r < 2; r++) {
        int n = nb + tid + r * 256;
#pragma unroll
        for (int j = 0; j < 8; j++) {
            float2 v = unpack2(acc[r][j]);
            g_hpart[(ks * 16 + 2 * j + 0) * H1DIM + n] = v.x;
            g_hpart[(ks * 16 + 2 * j + 1) * H1DIM + n] = v.y;
        }
    }
}

// ---------------- 2b) reduce 128 partials: float4-coalesced + shfl over 8 lanes ----------------
__global__ void reduce_h_kernel(const float* __restrict__ b1) {
    cudaGridDependencySynchronize();
    cudaTriggerProgrammaticLaunchCompletion();
    int gid = blockIdx.x * 256 + threadIdx.x;   // 0..32767
    int lane = gid & 31;
    int warp = gid >> 5;                         // 0..1023
    int f4 = warp * 4 + (lane & 3);              // 0..4095 (float4 index into g_h)
    int sp0 = lane >> 2;                          // 0..7
    const float4* hp = (const float4*)g_hpart;   // [128][4096]
    float4 s = make_float4(0.f, 0.f, 0.f, 0.f);
#pragma unroll
    for (int t = 0; t < 16; t++) {
        float4 v = hp[(sp0 + t * 8) * 4096 + f4];
        s.x += v.x; s.y += v.y; s.z += v.z; s.w += v.w;
    }
#pragma unroll
    for (int d = 4; d <= 16; d <<= 1) {
        s.x += __shfl_xor_sync(0xFFFFFFFFu, s.x, d);
        s.y += __shfl_xor_sync(0xFFFFFFFFu, s.y, d);
        s.z += __shfl_xor_sync(0xFFFFFFFFu, s.z, d);
        s.w += __shfl_xor_sync(0xFFFFFFFFu, s.w, d);
    }
    if ((lane >> 2) == 0) {
        int n0 = (f4 * 4) & 1023;
        float4 r;
        r.x = fmaxf(s.x + b1[n0 + 0], 0.f);
        r.y = fmaxf(s.y + b1[n0 + 1], 0.f);
        r.z = fmaxf(s.z + b1[n0 + 2], 0.f);
        r.w = fmaxf(s.w + b1[n0 + 3], 0.f);
        ((float4*)g_h)[f4] = r;
    }
}

// ---------------- 3) FC2: 256 m-tile x 32 k-slice, grid (8,32) ----------------
#define FC2_SWT_STRIDE 257
#define FC2_SH_STRIDE 18
__global__ void fc2_kernel(const float* __restrict__ W2) {
    extern __shared__ float sm2[];
    float* sWt = sm2;                        // [32 k][257]
    float* sh  = sm2 + 32 * FC2_SWT_STRIDE;  // [32 k][18]
    int tid = threadIdx.x;
    int m0 = blockIdx.x * 256;
    int ks = blockIdx.y;
    int k0 = ks * 32;
    int m = m0 + tid;

    // pre-sync prologue: W2 tile -> smem transposed (input only)
#pragma unroll
    for (int i = 0; i < 8; i++) {
        int f = tid + i * 256;
        int row = f >> 3, c = (f & 7) * 4;
        int mr = m0 + row;
        float4 v = make_float4(0.f, 0.f, 0.f, 0.f);
        if (mr < MDIM) v = *(const float4*)&W2[(size_t)mr * H1DIM + k0 + c];
        sWt[(c + 0) * FC2_SWT_STRIDE + row] = v.x;
        sWt[(c + 1) * FC2_SWT_STRIDE + row] = v.y;
        sWt[(c + 2) * FC2_SWT_STRIDE + row] = v.z;
        sWt[(c + 3) * FC2_SWT_STRIDE + row] = v.w;
    }
    cudaGridDependencySynchronize();
    cudaTriggerProgrammaticLaunchCompletion();

#pragma unroll
    for (int t = 0; t < 2; t++) {
        int e = tid + t * 256;
        int kk = e & 31, b = e >> 5;
        sh[kk * FC2_SH_STRIDE + b] = g_h[b * H1DIM + k0 + kk];
    }
    __syncthreads();

    u64p acc[8];
#pragma unroll
    for (int j = 0; j < 8; j++) acc[j] = 0;

#pragma unroll 4
    for (int kk = 0; kk < 32; kk++) {
        float w = sWt[kk * FC2_SWT_STRIDE + tid];
        u64p w2 = pack2(w, w);
        const u64p* fl = (const u64p*)&sh[kk * FC2_SH_STRIDE];
#pragma unroll
        for (int j = 0; j < 8; j++) FMA2(acc[j], fl[j], w2, acc[j]);
    }
    if (m < MDIM) {
#pragma unroll
        for (int j = 0; j < 8; j++) {
            float2 v = unpack2(acc[j]);
            g_logpart[(ks * 16 + 2 * j + 0) * 2048 + m] = v.x;
            g_logpart[(ks * 16 + 2 * j + 1) * 2048 + m] = v.y;
        }
    }
}

// ---------------- 4) epilogue: trigger at entry (gather prefetch overlaps) ----------------
__global__ void epi_kernel(const float* __restrict__ b2, float* __restrict__ out) {
    cudaTriggerProgrammaticLaunchCompletion();   // successor (gather) prologue reads p2 only
    cudaGridDependencySynchronize();
    int gid = blockIdx.x * 256 + threadIdx.x;   // 0..255999
    int e = gid >> 3;
    int r = gid & 7;
    int b = e / MDIM, m = e - b * MDIM;
    float s = 0.f;
#pragma unroll
    for (int t = 0; t < 4; t++) s += g_logpart[((r + t * 8) * 16 + b) * 2048 + m];
    s += __shfl_xor_sync(0xFFFFFFFFu, s, 1);
    s += __shfl_xor_sync(0xFFFFFFFFu, s, 2);
    s += __shfl_xor_sync(0xFFFFFFFFu, s, 4);
    if (r == 0) {
        float v = 1.f / (1.f + expf(-(s + b2[m])));
        out[OUT_INIT + b * MDIM + m] = v;
        int pt = m >> 1, c = m & 1;
        g_feat[((size_t)b * FDIM + 256 + c) * 1024 + pt] = v;
    }
}

// ---------------- 5) bilinear gather: cp.async image prefetch ----------------
__global__ void gather_kernel(const float* __restrict__ p2, const float* __restrict__ out) {
    extern __shared__ float img[];               // 64KB
    int bc = blockIdx.x;
    int b = bc >> 8;
    int tid = threadIdx.x;

    // pre-sync prologue: image -> smem via cp.async (input only; DMA streams
    // while this block waits at gridsync)
    unsigned int sbase = smem_u32(img);
    const char* gsrc = (const char*)(p2 + (size_t)bc * 16384);
#pragma unroll
    for (int t = 0; t < 16; t++) {
        int off = (tid + t * 256) * 16;
        asm volatile("cp.async.cg.shared.global [%0], [%1], 16;"
                     :: "r"(sbase + off), "l"(gsrc + off) : "memory");
    }
    asm volatile("cp.async.commit_group;" ::: "memory");
    cudaGridDependencySynchronize();
    cudaTriggerProgrammaticLaunchCompletion();

    const float* initp = out + OUT_INIT + b * MDIM;
    float px[4], py[4];
#pragma unroll
    for (int t = 0; t < 4; t++) {
        int pt = tid + t * 256;
        if (pt < NPTS) { px[t] = initp[pt * 2 + 0]; py[t] = initp[pt * 2 + 1]; }
    }
    asm volatile("cp.async.wait_group 0;" ::: "memory");
    __syncthreads();

    float* frow = &g_feat[((size_t)b * FDIM + (bc & 255)) * 1024];
#pragma unroll
    for (int t = 0; t < 4; t++) {
        int pt = tid + t * 256;
        if (pt < NPTS) {
            float x = px[t] * 128.f - 0.5f;
            float y = py[t] * 128.f - 0.5f;
            float x0f = floorf(x), y0f = floorf(y);
            int x0 = (int)x0f, y0 = (int)y0f;
            float wx = x - x0f, wy = y - y0f;
            bool xv0 = (x0 >= 0) & (x0 <= 127);
            bool xv1 = (x0 + 1 >= 0) & (x0 + 1 <= 127);
            bool yv0 = (y0 >= 0) & (y0 <= 127);
            bool yv1 = (y0 + 1 >= 0) & (y0 + 1 <= 127);
            int x0c = min(max(x0, 0), 127), x1c = min(max(x0 + 1, 0), 127);
            int y0c = min(max(y0, 0), 127), y1c = min(max(y0 + 1, 0), 127);
            float v00 = (xv0 && yv0) ? img[y0c * 128 + x0c] : 0.f;
            float v10 = (xv1 && yv0) ? img[y0c * 128 + x1c] : 0.f;
            float v01 = (xv0 && yv1) ? img[y1c * 128 + x0c] : 0.f;
            float v11 = (xv1 && yv1) ? img[y1c * 128 + x1c] : 0.f;
            frow[pt] = v00 * (1.f - wx) * (1.f - wy) + v10 * wx * (1.f - wy)
                     + v01 * (1.f - wx) * wy        + v11 * wx * wy;
        }
    }
}

// ---------------- 6) refine MLP: streamed k-chunks, 82432 B smem ----------------
__global__ void refine_kernel(const float* __restrict__ rb1,
                              const float* __restrict__ rb2,
                              const float* __restrict__ R3, const float* __restrict__ rb3,
                              float* __restrict__ out) {
    extern __shared__ float smr[];
    float* sh1    = smr;            // [128][64]
    float* sfeatc = smr + 8192;     // [32][64]   (layer1)  | sR2t overlays @8192 (layer2)
    float* sR1    = smr + 10240;    // [32][128]  (layer1)
    float* scoord = smr + 14336;    // [2][64]
    float* sR2t   = smr + 8192;     // [128][64]  (layer2)
    float* sh2    = smr + 16384;    // [64][64]
    float* sR3    = smr + 20480;    // [128]

    int tid = threadIdx.x;
    int b = blockIdx.y;
    int p0 = blockIdx.x * 64;
    int pg = tid & 15;
    int ng = tid >> 4;
    int n0 = ng * 8;

    // pre-sync prologue: coord rows (epi complete by PDL chain), R3, R1 chunk 0.
    if (tid < 128) {
        scoord[tid] = g_feat[((size_t)b * FDIM + 256 + (tid >> 6)) * 1024 + p0 + (tid & 63)];
        sR3[tid] = R3[tid];
    }
#pragma unroll
    for (int t = 0; t < 4; t++) {
        int f = tid + t * 256;
        ((float4*)sR1)[f] = ((const float4*)g_R1t)[f];
    }
    cudaGridDependencySynchronize();
    cudaTriggerProgrammaticLaunchCompletion();

    u64p acc[8][2];
#pragma unroll
    for (int r = 0; r < 8; r++) { acc[r][0] = 0; acc[r][1] = 0; }

    for (int kc = 0; kc < 256; kc += 32) {
        __syncthreads();
#pragma unroll
        for (int t = 0; t < 2; t++) {
            int f = tid + t * 256;
            int row = f >> 4, col = f & 15;
            ((float4*)sfeatc)[row * 16 + col] =
                *(const float4*)&g_feat[((size_t)b * FDIM + kc + row) * 1024 + p0 + col * 4];
        }
        if (kc > 0) {
#pragma unroll
            for (int t = 0; t < 4; t++) {
                int f = tid + t * 256;
                ((float4*)sR1)[f] = ((const float4*)(g_R1t + kc * 128))[f];
            }
        }
        __syncthreads();
#pragma unroll 2
        for (int kk = 0; kk < 32; kk++) {
            u64p w2[8];
#pragma unroll
            for (int r = 0; r < 8; r += 4) {
                float4 w4 = *(const float4*)&sR1[kk * 128 + n0 + r];
                w2[r + 0] = pack2(w4.x, w4.x); w2[r + 1] = pack2(w4.y, w4.y);
                w2[r + 2] = pack2(w4.z, w4.z); w2[r + 3] = pack2(w4.w, w4.w);
            }
            ulonglong2 f = *(const ulonglong2*)&sfeatc[kk * 64 + pg * 4];
#pragma unroll
            for (int r = 0; r < 8; r++) {
                FMA2(acc[r][0], f.x, w2[r], acc[r][0]);
                FMA2(acc[r][1], f.y, w2[r], acc[r][1]);
            }
        }
    }
#pragma unroll
    for (int kr = 0; kr < 2; kr++) {
        ulonglong2 f = *(const ulonglong2*)&scoord[kr * 64 + pg * 4];
#pragma unroll
        for (int r = 0; r < 8; r++) {
            float w = g_R1t[(256 + kr) * 128 + n0 + r];
            u64p w2 = pack2(w, w);
            FMA2(acc[r][0], f.x, w2, acc[r][0]);
            FMA2(acc[r][1], f.y, w2, acc[r][1]);
        }
    }
#pragma unroll
    for (int r = 0; r < 8; r++) {
        float bias = rb1[n0 + r];
        float2 v0 = unpack2(acc[r][0]), v1 = unpack2(acc[r][1]);
        float* d = &sh1[(n0 + r) * 64 + pg * 4];
        d[0] = fmaxf(v0.x + bias, 0.f); d[1] = fmaxf(v0.y + bias, 0.f);
        d[2] = fmaxf(v1.x + bias, 0.f); d[3] = fmaxf(v1.y + bias, 0.f);
    }
    __syncthreads();

    // ---- layer 2 ----
#pragma unroll
    for (int t = 0; t < 8; t++) {
        int f = tid + t * 256;
        ((float4*)sR2t)[f] = ((const float4*)g_R2t)[f];
    }
    __syncthreads();

    int n2 = ng * 4;
    u64p acc2[4][2];
#pragma unroll
    for (int r = 0; r < 4; r++) { acc2[r][0] = 0; acc2[r][1] = 0; }
#pragma unroll 2
    for (int kk = 0; kk < 128; kk++) {
        float4 w4 = *(const float4*)&sR2t[kk * 64 + n2];
        u64p w2[4] = { pack2(w4.x, w4.x), pack2(w4.y, w4.y),
                       pack2(w4.z, w4.z), pack2(w4.w, w4.w) };
        ulonglong2 f = *(const ulonglong2*)&sh1[kk * 64 + pg * 4];
#pragma unroll
        for (int r = 0; r < 4; r++) {
            FMA2(acc2[r][0], f.x, w2[r], acc2[r][0]);
            FMA2(acc2[r][1], f.y, w2[r], acc2[r][1]);
        }
    }
#pragma unroll
    for (int r = 0; r < 4; r++) {
        float bias = rb2[n2 + r];
        float2 v0 = unpack2(acc2[r][0]), v1 = unpack2(acc2[r][1]);
        float* d = &sh2[(n2 + r) * 64 + pg * 4];
        d[0] = fmaxf(v0.x + bias, 0.f); d[1] = fmaxf(v0.y + bias, 0.f);
        d[2] = fmaxf(v1.x + bias, 0.f); d[3] = fmaxf(v1.y + bias, 0.f);
    }
    __syncthreads();

    if (tid < 128) {
        int c = tid >> 6, pp = tid & 63;
        float a = rb3[c];
#pragma unroll 8
        for (int k = 0; k < 64; k++) a += sh2[k * 64 + pp] * sR3[c * 64 + k];
        float disp = tanhf(a);
        int ptg = p0 + pp;
        if (ptg < NPTS) {
            float iv = out[OUT_INIT + b * MDIM + ptg * 2 + c];
            float r = fminf(fmaxf(iv + 0.1f * disp, 0.f), 1.f);
            out[(b * NPTS + ptg) * 2 + c] = r;
        }
    }
}

// ---------------- 7) value head ----------------
__global__ void value_kernel(const float* __restrict__ V1, const float* __restrict__ vb1,
                             const float* __restrict__ V2, const float* __restrict__ vb2,
                             float* __restrict__ out) {
    extern __shared__ float sv[];
    float* spf  = sv;
    float* sV1  = sv + 128;
    float* sred = sv + 128 + 12800;
    int bp = blockIdx.x;
    int tid = threadIdx.x;

    const float4* v4 = (const float4*)V1;
    float4* s4 = (float4*)sV1;
#pragma unroll
    for (int t = 0; t < 25; t++) s4[tid + t * 128] = v4[tid + t * 128];
    cudaGridDependencySynchronize();

    if (tid < 100) spf[tid] = out[bp * 100 + tid];
    __syncthreads();
    float a = vb1[tid];
#pragma unroll 4
    for (int k = 0; k < 100; k++) a += spf[k] * sV1[tid * 100 + k];
    sred[tid] = fmaxf(a, 0.f) * V2[tid];
    __syncthreads();
#pragma unroll
    for (int s = 64; s > 0; s >>= 1) {
        if (tid < s) sred[tid] += sred[tid + s];
        __syncthreads();
    }
    if (tid == 0) out[OUT_V + bp] = 1.f / (1.f + expf(-(sred[0] + vb2[0])));
}

// ---------------- launch ----------------
extern "C" void kernel_launch(void* const* d_in, const int* in_sizes, int n_in,
                              void* d_out, int out_size) {
    const float* p4   = (const float*)d_in[0];
    const float* p2   = (const float*)d_in[1];
    const float* W1   = (const float*)d_in[3];
    const float* b1   = (const float*)d_in[4];
    const float* W2   = (const float*)d_in[5];
    const float* b2   = (const float*)d_in[6];
    const float* R1   = (const float*)d_in[7];
    const float* rb1  = (const float*)d_in[8];
    const float* R2   = (const float*)d_in[9];
    const float* rb2  = (const float*)d_in[10];
    const float* R3   = (const float*)d_in[11];
    const float* rb3  = (const float*)d_in[12];
    const float* V1   = (const float*)d_in[13];
    const float* vb1  = (const float*)d_in[14];
    const float* V2   = (const float*)d_in[15];
    const float* vb2  = (const float*)d_in[16];
    float* out = (float*)d_out;

    const int FC1_SMEM = (512 * FC1_SW_STRIDE + 128 * FC1_SF_STRIDE) * 4;   // 76800
    const int FC2_SMEM = (32 * FC2_SWT_STRIDE + 32 * FC2_SH_STRIDE) * 4;    // 35200
    const int RFN_SMEM = 20608 * 4;                                         // 82432

    cudaFuncSetAttribute(fc1_kernel,    cudaFuncAttributeMaxDynamicSharedMemorySize, FC1_SMEM);
    cudaFuncSetAttribute(fc2_kernel,    cudaFuncAttributeMaxDynamicSharedMemorySize, FC2_SMEM);
    cudaFuncSetAttribute(gather_kernel, cudaFuncAttributeMaxDynamicSharedMemorySize, 65536);
    cudaFuncSetAttribute(refine_kernel, cudaFuncAttributeMaxDynamicSharedMemorySize, RFN_SMEM);
    cudaFuncSetAttribute(value_kernel,  cudaFuncAttributeMaxDynamicSharedMemorySize, 52224);

    cudaLaunchAttribute pdl[1];
    pdl[0].id = cudaLaunchAttributeProgrammaticStreamSerialization;
    pdl[0].val.programmaticStreamSerializationAllowed = 1;

    pool_kernel<<<1186, 256>>>(p4, R1, R2);

    cudaLaunchConfig_t cfg = {};
    cfg.blockDim = {256, 1, 1};
    cfg.stream = 0;
    cfg.attrs = pdl;
    cfg.numAttrs = 1;

    cfg.gridDim = {128, 2, 1};  cfg.dynamicSmemBytes = FC1_SMEM;
    cudaLaunchKernelEx(&cfg, fc1_kernel, W1);
    cfg.gridDim = {128, 1, 1};  cfg.dynamicSmemBytes = 0;
    cudaLaunchKernelEx(&cfg, reduce_h_kernel, b1);
    cfg.gridDim = {8, 32, 1};   cfg.dynamicSmemBytes = FC2_SMEM;
    cudaLaunchKernelEx(&cfg, fc2_kernel, W2);
    cfg.gridDim = {1000, 1, 1}; cfg.dynamicSmemBytes = 0;
    cudaLaunchKernelEx(&cfg, epi_kernel, b2, out);
    cfg.gridDim = {4096, 1, 1}; cfg.dynamicSmemBytes = 65536;
    cudaLaunchKernelEx(&cfg, gather_kernel, p2, out);
    cfg.gridDim = {16, 16, 1};  cfg.dynamicSmemBytes = RFN_SMEM;
    cudaLaunchKernelEx(&cfg, refine_kernel, rb1, rb2, R3, rb3, out);
    cfg.gridDim = {320, 1, 1};  cfg.blockDim = {128, 1, 1}; cfg.dynamicSmemBytes = 52224;
    cudaLaunchKernelEx(&cfg, value_kernel, V1, vb1, V2, vb2, out);
}